// round 6
// baseline (speedup 1.0000x reference)
#include <cuda_runtime.h>

#define FULLMASK 0xffffffffu

// ---------------- scratch (__device__ globals; no allocation allowed) ----------------
__device__ __align__(16) unsigned g_X1[6*784*40];      // packed bip(image, rm_in1)
__device__ __align__(16) unsigned g_W1[6*25*40];       // packed bip(w1, rm_k1)
__device__ __align__(16) unsigned g_W2[16*6*25*40];    // packed bip(w2, rm_k2)
__device__ __align__(16) unsigned g_X2[16*6*144*40];   // packed bip(p1norm, rm_in2)
__device__ __align__(16) unsigned g_SW3[120*256*40];   // [m][n][40]
__device__ __align__(16) unsigned g_SW4[84*120*40];    // [m][n][40]
__device__ __align__(16) unsigned g_SW5[10*84*40];     // [m][n][40]
__device__ __align__(16) unsigned g_X3[256*40];
__device__ __align__(16) unsigned g_X4[120*40];
__device__ __align__(16) unsigned g_X5[84*40];
__device__ int g_pos3[120];
__device__ int g_pos4[84];
__device__ int g_pos5[10];
__device__ float g_P1[864];       // pool1 (6,12,12) un-normalized
__device__ float g_P2[256];       // pool2 (16,4,4) un-normalized
__device__ float g_f1[120];       // relu(fc3) un-normalized
__device__ float g_f2[84];        // relu(fc4) un-normalized
__device__ unsigned g_mm[8];      // bit-punned nonneg float min/max: [0,1]=pool1 [2,3]=pool2 [4,5]=fc3 [6,7]=fc4
__device__ unsigned g_bar_arrive; // grid barrier state (zero-init; self-resetting)
__device__ unsigned g_bar_gen;

// ---------------- helpers ----------------

// Pack one bitstream row: 1280 floats -> 40 uint32 words. bit j of word wd = (thr > rm[wd*32+j]).
__device__ __forceinline__ void pack_row(const float* __restrict__ src, float thr,
                                         unsigned* __restrict__ dst, int lane) {
#pragma unroll
    for (int wd = 0; wd < 40; wd += 4) {
        float v0 = src[(wd+0)*32 + lane];
        float v1 = src[(wd+1)*32 + lane];
        float v2 = src[(wd+2)*32 + lane];
        float v3 = src[(wd+3)*32 + lane];
        unsigned b0 = __ballot_sync(FULLMASK, thr > v0);
        unsigned b1 = __ballot_sync(FULLMASK, thr > v1);
        unsigned b2 = __ballot_sync(FULLMASK, thr > v2);
        unsigned b3 = __ballot_sync(FULLMASK, thr > v3);
        if (lane == 0) *reinterpret_cast<uint4*>(dst + wd) = make_uint4(b0, b1, b2, b3);
    }
}

// Same, but return popcount of the whole row (ballots are warp-uniform, so sum is uniform).
__device__ __forceinline__ int pack_row_popc(const float* __restrict__ src, float thr, int lane) {
    int s = 0;
#pragma unroll
    for (int wd = 0; wd < 40; wd += 4) {
        float v0 = src[(wd+0)*32 + lane];
        float v1 = src[(wd+1)*32 + lane];
        float v2 = src[(wd+2)*32 + lane];
        float v3 = src[(wd+3)*32 + lane];
        s += __popc(__ballot_sync(FULLMASK, thr > v0));
        s += __popc(__ballot_sync(FULLMASK, thr > v1));
        s += __popc(__ballot_sync(FULLMASK, thr > v2));
        s += __popc(__ballot_sync(FULLMASK, thr > v3));
    }
    return s;
}

__device__ __forceinline__ float thr_of(float v) {
    return __fmul_rn(__fadd_rn(v, 1.0f), 0.5f);
}

// Grid-wide barrier for a co-resident grid (nblocks <= #SMs guaranteed resident).
// Self-resetting; g_bar_gen increments monotonically across barriers and replays.
__device__ __forceinline__ void grid_bar(int nblocks) {
    __syncthreads();
    if (threadIdx.x == 0) {
        __threadfence();
        unsigned gen = atomicAdd(&g_bar_gen, 0u);
        if (atomicAdd(&g_bar_arrive, 1u) == (unsigned)(nblocks - 1)) {
            atomicExch(&g_bar_arrive, 0u);
            __threadfence();
            atomicAdd(&g_bar_gen, 1u);
        } else {
            while (atomicAdd(&g_bar_gen, 0u) == gen) {}
            __threadfence();
        }
    }
    __syncthreads();
}

// ---------------- kernel 1: all static packing (241MB HBM) + g_mm init ----------------
__global__ void k_pack_static_all(const float* __restrict__ img, const float* __restrict__ w1,
                                  const float* __restrict__ w2,
                                  const float* __restrict__ wfc3, const float* __restrict__ wfc4,
                                  const float* __restrict__ wfc5,
                                  const float* __restrict__ bfc3, const float* __restrict__ bfc4,
                                  const float* __restrict__ bfc5,
                                  const float* __restrict__ rm_in1, const float* __restrict__ rm_k1,
                                  const float* __restrict__ rm_k2,
                                  const float* __restrict__ rm_w3, const float* __restrict__ rm_w4,
                                  const float* __restrict__ rm_w5,
                                  const float* __restrict__ rm_b3, const float* __restrict__ rm_b4,
                                  const float* __restrict__ rm_b5) {
    if (blockIdx.x == 0 && threadIdx.x < 8)
        g_mm[threadIdx.x] = (threadIdx.x & 1) ? 0u : 0x7f800000u;  // min=+inf, max=0

    int lane = threadIdx.x & 31;
    int gw = (blockIdx.x * blockDim.x + threadIdx.x) >> 5;
    int nw = (gridDim.x * blockDim.x) >> 5;
    const int RX1 = 6*784;               // 4704
    const int RW1 = RX1 + 6*25;          // 4854
    const int RW2 = RW1 + 16*6*25;       // 7254
    const int RS3 = RW2 + 256*120;       // 37974
    const int RS4 = RS3 + 120*84;        // 48054
    const int RS5 = RS4 + 84*10;         // 48894
    const int RB3 = RS5 + 120;
    const int RB4 = RB3 + 84;
    const int RB5 = RB4 + 10;            // 49108
    for (int row = gw; row < RB5; row += nw) {
        if (row < RX1) {
            pack_row(rm_in1 + (size_t)row * 1280, thr_of(img[row % 784]), g_X1 + row*40, lane);
        } else if (row < RW1) {
            int r = row - RX1;
            pack_row(rm_k1 + (size_t)r * 1280, thr_of(w1[r]), g_W1 + r*40, lane);
        } else if (row < RW2) {
            int r = row - RW1;
            pack_row(rm_k2 + (size_t)r * 1280, thr_of(w2[r]), g_W2 + r*40, lane);
        } else if (row < RS3) {
            int r = row - RW2; int n = r / 120, m = r % 120;   // rm_w3 is [n][m][l]
            pack_row(rm_w3 + (size_t)r * 1280, thr_of(wfc3[r]), g_SW3 + (m*256 + n)*40, lane);
        } else if (row < RS4) {
            int r = row - RS3; int n = r / 84, m = r % 84;
            pack_row(rm_w4 + (size_t)r * 1280, thr_of(wfc4[r]), g_SW4 + (m*120 + n)*40, lane);
        } else if (row < RS5) {
            int r = row - RS4; int n = r / 10, m = r % 10;
            pack_row(rm_w5 + (size_t)r * 1280, thr_of(wfc5[r]), g_SW5 + (m*84 + n)*40, lane);
        } else if (row < RB3) {
            int r = row - RS5;
            int s = pack_row_popc(rm_b3 + (size_t)r * 1280, thr_of(bfc3[r]), lane);
            if (lane == 0) g_pos3[r] = s;
        } else if (row < RB4) {
            int r = row - RB3;
            int s = pack_row_popc(rm_b4 + (size_t)r * 1280, thr_of(bfc4[r]), lane);
            if (lane == 0) g_pos4[r] = s;
        } else {
            int r = row - RB4;
            int s = pack_row_popc(rm_b5 + (size_t)r * 1280, thr_of(bfc5[r]), lane);
            if (lane == 0) g_pos5[r] = s;
        }
    }
}

// ---------------- kernel 2: conv1 + pool1 fused. warp = pool cell (4 windows). ----------------
__global__ void k_conv1pool1(const float* __restrict__ b1) {   // <<<108,256>>> = 864 warps
    int lane = threadIdx.x & 31;
    int gw = (blockIdx.x * blockDim.x + threadIdx.x) >> 5;     // 0..863 = pool cell
    int o = gw / 144, rem = gw % 144, pr = rem / 12, pc = rem % 12;
    const unsigned* xb = g_X1 + o*784*40;
    const unsigned* wb = g_W1 + o*25*40;
    float bo = b1[o];
    float m = 0.0f;
#pragma unroll
    for (int win = 0; win < 4; ++win) {
        int r = 2*pr + (win >> 1), c = 2*pc + (win & 1);
        int ham = 0;
#pragma unroll
        for (int k = 0; k < 25; ++k) {
            int n = (r + k/5)*28 + (c + k%5);
            const unsigned* xr = xb + n*40;
            const unsigned* wr = wb + k*40;
            for (int wd = lane; wd < 40; wd += 32) ham += __popc(xr[wd] ^ wr[wd]);
        }
        ham = __reduce_add_sync(FULLMASK, ham);
        // count = 32000 - H; out = (2*(count*(1/32000))-1)*25 + b; relu
        float cnt = (float)(32000 - ham);
        float q = __fmul_rn(cnt, (1.0f/32000.0f));
        float y = __fsub_rn(__fmul_rn(2.0f, q), 1.0f);
        float v = fmaxf(__fadd_rn(__fmul_rn(y, 25.0f), bo), 0.0f);
        m = fmaxf(m, v);
    }
    if (lane == 0) {
        g_P1[gw] = m;
        atomicMin(&g_mm[0], __float_as_uint(m));
        atomicMax(&g_mm[1], __float_as_uint(m));
    }
}

// ---------------- kernel 3: pack X2 (71MB rm_in2) ----------------
__global__ void k_pack_X2(const float* __restrict__ rm_in2) {  // <<<1728,256>>> = 13824 warps
    int lane = threadIdx.x & 31;
    int row = (blockIdx.x * blockDim.x + threadIdx.x) >> 5;    // 0..13823
    float mn = __uint_as_float(g_mm[0]);
    float mx = __uint_as_float(g_mm[1]);
    float den = mx - mn;
    float p = g_P1[row % 864];                                 // row=(o*6+i)*144+n; %864 = i*144+n
    float pv = __fdiv_rn(p - mn, den);                         // norm01 (runtime denom: true div)
    pack_row(rm_in2 + (size_t)row * 1280, thr_of(pv), g_X2 + row*40, lane);
}

// ---------------- kernel 4: fused tail (conv2+pool2 -> packX3 -> fc3 -> packX4 -> fc4 -> packX5 -> fc5) ----------------
#define TAIL_BLOCKS 128
__global__ void k_tail(const float* __restrict__ b2,
                       const float* __restrict__ rm_x3, const float* __restrict__ rm_x4,
                       const float* __restrict__ rm_x5, float* __restrict__ out) {
    __shared__ int shi[256];
    __shared__ float shf[8];
    int t = threadIdx.x;
    int lane = t & 31;
    int wid = t >> 5;
    int gw = blockIdx.x * 8 + wid;    // global warp 0..1023

    // ---- Phase A: conv2 + pool2 (+ min/max). 256 pool cells; block handles 2; warp = 1 window.
    {
        int cellIdx = blockIdx.x * 2 + (wid >> 2);     // 0..255
        int o = cellIdx >> 4, rem = cellIdx & 15, pr = rem >> 2, pc = rem & 3;
        int win = wid & 3;
        int r = 2*pr + (win >> 1), c = 2*pc + (win & 1);
        int ham = 0;
        for (int idx = lane; idx < 6000; idx += 32) {
            int wd = idx % 40; int rest = idx / 40; int k = rest % 25; int i = rest / 25;
            int n = (r + k/5)*12 + (c + k%5);
            ham += __popc(g_X2[((o*6 + i)*144 + n)*40 + wd] ^ g_W2[((o*6 + i)*25 + k)*40 + wd]);
        }
        ham = __reduce_add_sync(FULLMASK, ham);
        if (lane == 0) {
            float cnt = (float)(192000 - ham);
            float q = __fmul_rn(cnt, (1.0f/192000.0f));
            float y = __fsub_rn(__fmul_rn(2.0f, q), 1.0f);
            float v = __fadd_rn(__fmul_rn(y, 150.0f), b2[o]);
            shf[wid] = fmaxf(v, 0.0f);
        }
        __syncthreads();
        if (t < 2) {
            int ci = blockIdx.x * 2 + t;
            float m = fmaxf(fmaxf(shf[t*4+0], shf[t*4+1]), fmaxf(shf[t*4+2], shf[t*4+3]));
            g_P2[ci] = m;
            atomicMin(&g_mm[2], __float_as_uint(m));
            atomicMax(&g_mm[3], __float_as_uint(m));
        }
    }
    grid_bar(TAIL_BLOCKS);

    // ---- Phase B: pack X3 (256 rows from rm_x3)
    {
        float mn = __uint_as_float(g_mm[2]);
        float mx = __uint_as_float(g_mm[3]);
        float den = mx - mn;
        if (gw < 256) {
            float pv = __fdiv_rn(g_P2[gw] - mn, den);
            pack_row(rm_x3 + (size_t)gw * 1280, thr_of(pv), g_X3 + gw*40, lane);
        }
    }
    grid_bar(TAIL_BLOCKS);

    // ---- Phase C: fc3 (120 outputs; block m, thread t = input n)
    {
        int h = 0;
        if (blockIdx.x < 120) {
            const unsigned* xr = g_X3 + t*40;
            const unsigned* sr = g_SW3 + (blockIdx.x*256 + t)*40;
#pragma unroll
            for (int wd = 0; wd < 40; ++wd) h += __popc(xr[wd] ^ sr[wd]);
        }
        shi[t] = h; __syncthreads();
        for (int s = 128; s; s >>= 1) { if (t < s) shi[t] += shi[t + s]; __syncthreads(); }
        if (t == 0 && blockIdx.x < 120) {
            float cnt = (float)(327680 - shi[0] + g_pos3[blockIdx.x]);   // 256*1280 - H + pos
            float q = __fmul_rn(cnt, (1.0f/328960.0f));                  // 257*1280
            float o3 = __fmul_rn(__fsub_rn(__fmul_rn(2.0f, q), 1.0f), 257.0f);
            float rv = fmaxf(o3, 0.0f);
            g_f1[blockIdx.x] = rv;
            atomicMin(&g_mm[4], __float_as_uint(rv));
            atomicMax(&g_mm[5], __float_as_uint(rv));
        }
    }
    grid_bar(TAIL_BLOCKS);

    // ---- Phase D: pack X4 (120 rows from rm_x4)
    {
        float mn = __uint_as_float(g_mm[4]);
        float mx = __uint_as_float(g_mm[5]);
        float den = mx - mn;
        if (gw < 120) {
            float pv = __fdiv_rn(g_f1[gw] - mn, den);
            pack_row(rm_x4 + (size_t)gw * 1280, thr_of(pv), g_X4 + gw*40, lane);
        }
    }
    grid_bar(TAIL_BLOCKS);

    // ---- Phase E: fc4 (84 outputs; block m, thread t<120 = input n)
    {
        int h = 0;
        if (blockIdx.x < 84 && t < 120) {
            const unsigned* xr = g_X4 + t*40;
            const unsigned* sr = g_SW4 + (blockIdx.x*120 + t)*40;
#pragma unroll
            for (int wd = 0; wd < 40; ++wd) h += __popc(xr[wd] ^ sr[wd]);
        }
        shi[t] = h; __syncthreads();
        for (int s = 128; s; s >>= 1) { if (t < s) shi[t] += shi[t + s]; __syncthreads(); }
        if (t == 0 && blockIdx.x < 84) {
            float cnt = (float)(153600 - shi[0] + g_pos4[blockIdx.x]);   // 120*1280 - H + pos
            float q = __fmul_rn(cnt, (1.0f/154880.0f));                  // 121*1280
            float o4 = __fmul_rn(__fsub_rn(__fmul_rn(2.0f, q), 1.0f), 121.0f);
            float rv = fmaxf(o4, 0.0f);
            g_f2[blockIdx.x] = rv;
            atomicMin(&g_mm[6], __float_as_uint(rv));
            atomicMax(&g_mm[7], __float_as_uint(rv));
        }
    }
    grid_bar(TAIL_BLOCKS);

    // ---- Phase F: pack X5 (84 rows from rm_x5)
    {
        float mn = __uint_as_float(g_mm[6]);
        float mx = __uint_as_float(g_mm[7]);
        float den = mx - mn;
        if (gw < 84) {
            float pv = __fdiv_rn(g_f2[gw] - mn, den);
            pack_row(rm_x5 + (size_t)gw * 1280, thr_of(pv), g_X5 + gw*40, lane);
        }
    }
    grid_bar(TAIL_BLOCKS);

    // ---- Phase G: fc5 (10 outputs; block m, thread t<84 = input n)
    {
        int h = 0;
        if (blockIdx.x < 10 && t < 84) {
            const unsigned* xr = g_X5 + t*40;
            const unsigned* sr = g_SW5 + (blockIdx.x*84 + t)*40;
#pragma unroll
            for (int wd = 0; wd < 40; ++wd) h += __popc(xr[wd] ^ sr[wd]);
        }
        shi[t] = h; __syncthreads();
        for (int s = 128; s; s >>= 1) { if (t < s) shi[t] += shi[t + s]; __syncthreads(); }
        if (t == 0 && blockIdx.x < 10) {
            float cnt = (float)(107520 - shi[0] + g_pos5[blockIdx.x]);   // 84*1280 - H + pos
            float q = __fmul_rn(cnt, (1.0f/108800.0f));                  // 85*1280
            out[blockIdx.x] = __fmul_rn(__fsub_rn(__fmul_rn(2.0f, q), 1.0f), 85.0f);
        }
    }
}

// ---------------- launch ----------------
extern "C" void kernel_launch(void* const* d_in, const int* in_sizes, int n_in,
                              void* d_out, int out_size) {
    const float* img    = (const float*)d_in[0];
    const float* w1     = (const float*)d_in[1];
    const float* b1     = (const float*)d_in[2];
    const float* w2     = (const float*)d_in[3];
    const float* b2     = (const float*)d_in[4];
    const float* wfc3   = (const float*)d_in[5];
    const float* bfc3   = (const float*)d_in[6];
    const float* wfc4   = (const float*)d_in[7];
    const float* bfc4   = (const float*)d_in[8];
    const float* wfc5   = (const float*)d_in[9];
    const float* bfc5   = (const float*)d_in[10];
    const float* rm_in1 = (const float*)d_in[11];
    const float* rm_k1  = (const float*)d_in[12];
    const float* rm_in2 = (const float*)d_in[13];
    const float* rm_k2  = (const float*)d_in[14];
    const float* rm_x3  = (const float*)d_in[15];
    const float* rm_w3  = (const float*)d_in[16];
    const float* rm_b3  = (const float*)d_in[17];
    const float* rm_x4  = (const float*)d_in[18];
    const float* rm_w4  = (const float*)d_in[19];
    const float* rm_b4  = (const float*)d_in[20];
    const float* rm_x5  = (const float*)d_in[21];
    const float* rm_w5  = (const float*)d_in[22];
    const float* rm_b5  = (const float*)d_in[23];
    float* out = (float*)d_out;

    k_pack_static_all<<<2048, 256>>>(img, w1, w2, wfc3, wfc4, wfc5, bfc3, bfc4, bfc5,
                                     rm_in1, rm_k1, rm_k2, rm_w3, rm_w4, rm_w5,
                                     rm_b3, rm_b4, rm_b5);
    k_conv1pool1<<<108, 256>>>(b1);
    k_pack_X2<<<1728, 256>>>(rm_in2);
    k_tail<<<TAIL_BLOCKS, 256>>>(b2, rm_x3, rm_x4, rm_x5, out);
}

// round 7
// speedup vs baseline: 1.7331x; 1.7331x over previous
#include <cuda_runtime.h>

#define FULLMASK 0xffffffffu

// ---------------- scratch (__device__ globals; no allocation allowed) ----------------
__device__ __align__(16) unsigned g_X1[6*784*40];      // packed bip(image, rm_in1)
__device__ __align__(16) unsigned g_W1[6*25*40];       // packed bip(w1, rm_k1)
__device__ __align__(16) unsigned g_W2[16*6*25*40];    // packed bip(w2, rm_k2)
__device__ __align__(16) unsigned g_X2[16*6*144*40];   // packed bip(p1norm, rm_in2)
__device__ __align__(16) unsigned g_SW3[120*256*40];   // [m][n][40]
__device__ __align__(16) unsigned g_SW4[84*120*40];    // [m][n][40]
__device__ __align__(16) unsigned g_SW5[10*84*40];     // [m][n][40]
__device__ __align__(16) unsigned g_X3[256*40];
__device__ __align__(16) unsigned g_X4[120*40];
__device__ __align__(16) unsigned g_X5[84*40];
__device__ int g_pos3[120];
__device__ int g_pos4[84];
__device__ int g_pos5[10];
__device__ float g_P1[864];       // pool1 (6,12,12) un-normalized
__device__ float g_P2[256];       // pool2 (16,4,4) un-normalized
__device__ float g_f1[120];       // relu(fc3) un-normalized
__device__ float g_f2[84];        // relu(fc4) un-normalized
__device__ unsigned g_mm[8];      // bit-punned nonneg float min/max: [0,1]=pool1 [2,3]=pool2 [4,5]=fc3 [6,7]=fc4
__device__ unsigned g_bar_arrive; // grid barrier state (zero-init; self-resetting)
__device__ unsigned g_bar_gen;

// ---------------- helpers ----------------

__device__ __forceinline__ int popc4(uint4 a, uint4 b) {
    return __popc(a.x ^ b.x) + __popc(a.y ^ b.y) + __popc(a.z ^ b.z) + __popc(a.w ^ b.w);
}

// Pack one bitstream row: 1280 floats -> 40 uint32 words. bit j of word wd = (thr > rm[wd*32+j]).
// All 40 loads hoisted before the ballot chain for max MLP.
__device__ __forceinline__ void pack_row(const float* __restrict__ src, float thr,
                                         unsigned* __restrict__ dst, int lane) {
    float v[40];
#pragma unroll
    for (int wd = 0; wd < 40; ++wd) v[wd] = src[wd*32 + lane];
#pragma unroll
    for (int wd = 0; wd < 40; wd += 4) {
        unsigned b0 = __ballot_sync(FULLMASK, thr > v[wd+0]);
        unsigned b1 = __ballot_sync(FULLMASK, thr > v[wd+1]);
        unsigned b2 = __ballot_sync(FULLMASK, thr > v[wd+2]);
        unsigned b3 = __ballot_sync(FULLMASK, thr > v[wd+3]);
        if (lane == 0) *reinterpret_cast<uint4*>(dst + wd) = make_uint4(b0, b1, b2, b3);
    }
}

// Same, but return popcount of the whole row (ballots are warp-uniform, so sum is uniform).
__device__ __forceinline__ int pack_row_popc(const float* __restrict__ src, float thr, int lane) {
    float v[40];
#pragma unroll
    for (int wd = 0; wd < 40; ++wd) v[wd] = src[wd*32 + lane];
    int s = 0;
#pragma unroll
    for (int wd = 0; wd < 40; ++wd) s += __popc(__ballot_sync(FULLMASK, thr > v[wd]));
    return s;
}

__device__ __forceinline__ float thr_of(float v) {
    return __fmul_rn(__fadd_rn(v, 1.0f), 0.5f);
}

// Grid-wide barrier for a co-resident grid (nblocks <= #SMs). Arrival = one atomicAdd;
// waiters poll with volatile LOADS (no RMW contention) + nanosleep backoff.
__device__ __forceinline__ void grid_bar(int nblocks) {
    __syncthreads();
    if (threadIdx.x == 0) {
        __threadfence();
        unsigned gen = *(volatile unsigned*)&g_bar_gen;
        if (atomicAdd(&g_bar_arrive, 1u) == (unsigned)(nblocks - 1)) {
            atomicExch(&g_bar_arrive, 0u);
            __threadfence();
            atomicAdd(&g_bar_gen, 1u);
        } else {
            while (*(volatile unsigned*)&g_bar_gen == gen) __nanosleep(64);
        }
        __threadfence();
    }
    __syncthreads();
}

// ---------------- kernel 1: all static packing (241MB HBM) + g_mm init ----------------
__global__ void k_pack_static_all(const float* __restrict__ img, const float* __restrict__ w1,
                                  const float* __restrict__ w2,
                                  const float* __restrict__ wfc3, const float* __restrict__ wfc4,
                                  const float* __restrict__ wfc5,
                                  const float* __restrict__ bfc3, const float* __restrict__ bfc4,
                                  const float* __restrict__ bfc5,
                                  const float* __restrict__ rm_in1, const float* __restrict__ rm_k1,
                                  const float* __restrict__ rm_k2,
                                  const float* __restrict__ rm_w3, const float* __restrict__ rm_w4,
                                  const float* __restrict__ rm_w5,
                                  const float* __restrict__ rm_b3, const float* __restrict__ rm_b4,
                                  const float* __restrict__ rm_b5) {
    if (blockIdx.x == 0 && threadIdx.x < 8)
        g_mm[threadIdx.x] = (threadIdx.x & 1) ? 0u : 0x7f800000u;  // min=+inf, max=0

    int lane = threadIdx.x & 31;
    int gw = (blockIdx.x * blockDim.x + threadIdx.x) >> 5;
    int nw = (gridDim.x * blockDim.x) >> 5;
    const int RX1 = 6*784;               // 4704
    const int RW1 = RX1 + 6*25;          // 4854
    const int RW2 = RW1 + 16*6*25;       // 7254
    const int RS3 = RW2 + 256*120;       // 37974
    const int RS4 = RS3 + 120*84;        // 48054
    const int RS5 = RS4 + 84*10;         // 48894
    const int RB3 = RS5 + 120;
    const int RB4 = RB3 + 84;
    const int RB5 = RB4 + 10;            // 49108
    for (int row = gw; row < RB5; row += nw) {
        if (row < RX1) {
            pack_row(rm_in1 + (size_t)row * 1280, thr_of(img[row % 784]), g_X1 + row*40, lane);
        } else if (row < RW1) {
            int r = row - RX1;
            pack_row(rm_k1 + (size_t)r * 1280, thr_of(w1[r]), g_W1 + r*40, lane);
        } else if (row < RW2) {
            int r = row - RW1;
            pack_row(rm_k2 + (size_t)r * 1280, thr_of(w2[r]), g_W2 + r*40, lane);
        } else if (row < RS3) {
            int r = row - RW2; int n = r / 120, m = r % 120;   // rm_w3 is [n][m][l]
            pack_row(rm_w3 + (size_t)r * 1280, thr_of(wfc3[r]), g_SW3 + (m*256 + n)*40, lane);
        } else if (row < RS4) {
            int r = row - RS3; int n = r / 84, m = r % 84;
            pack_row(rm_w4 + (size_t)r * 1280, thr_of(wfc4[r]), g_SW4 + (m*120 + n)*40, lane);
        } else if (row < RS5) {
            int r = row - RS4; int n = r / 10, m = r % 10;
            pack_row(rm_w5 + (size_t)r * 1280, thr_of(wfc5[r]), g_SW5 + (m*84 + n)*40, lane);
        } else if (row < RB3) {
            int r = row - RS5;
            int s = pack_row_popc(rm_b3 + (size_t)r * 1280, thr_of(bfc3[r]), lane);
            if (lane == 0) g_pos3[r] = s;
        } else if (row < RB4) {
            int r = row - RB3;
            int s = pack_row_popc(rm_b4 + (size_t)r * 1280, thr_of(bfc4[r]), lane);
            if (lane == 0) g_pos4[r] = s;
        } else {
            int r = row - RB4;
            int s = pack_row_popc(rm_b5 + (size_t)r * 1280, thr_of(bfc5[r]), lane);
            if (lane == 0) g_pos5[r] = s;
        }
    }
}

// ---------------- kernel 2: conv1 + pool1 fused. warp = pool cell (4 windows). ----------------
__global__ void k_conv1pool1(const float* __restrict__ b1) {   // <<<108,256>>> = 864 warps
    int lane = threadIdx.x & 31;
    int gw = (blockIdx.x * blockDim.x + threadIdx.x) >> 5;     // 0..863 = pool cell
    int o = gw / 144, rem = gw % 144, pr = rem / 12, pc = rem % 12;
    const uint4* xb = reinterpret_cast<const uint4*>(g_X1 + o*784*40);
    const uint4* wb = reinterpret_cast<const uint4*>(g_W1 + o*25*40);
    float bo = b1[o];
    float m = 0.0f;
#pragma unroll
    for (int win = 0; win < 4; ++win) {
        int r = 2*pr + (win >> 1), c = 2*pc + (win & 1);
        int ham = 0;
        for (int q = lane; q < 250; q += 32) {        // (tap k, quad) flattened: 25*10
            int k = q / 10, quad = q - 10*k;
            int n = (r + k/5)*28 + (c + k%5);
            ham += popc4(xb[n*10 + quad], wb[k*10 + quad]);
        }
        ham = __reduce_add_sync(FULLMASK, ham);
        // count = 32000 - H; out = (2*(count*(1/32000))-1)*25 + b; relu
        float cnt = (float)(32000 - ham);
        float q2 = __fmul_rn(cnt, (1.0f/32000.0f));
        float y = __fsub_rn(__fmul_rn(2.0f, q2), 1.0f);
        float v = fmaxf(__fadd_rn(__fmul_rn(y, 25.0f), bo), 0.0f);
        m = fmaxf(m, v);
    }
    if (lane == 0) {
        g_P1[gw] = m;
        atomicMin(&g_mm[0], __float_as_uint(m));
        atomicMax(&g_mm[1], __float_as_uint(m));
    }
}

// ---------------- kernel 3: pack X2 (71MB rm_in2) ----------------
__global__ void k_pack_X2(const float* __restrict__ rm_in2) {  // <<<1728,256>>> = 13824 warps
    int lane = threadIdx.x & 31;
    int row = (blockIdx.x * blockDim.x + threadIdx.x) >> 5;    // 0..13823
    float mn = __uint_as_float(g_mm[0]);
    float mx = __uint_as_float(g_mm[1]);
    float den = mx - mn;
    float p = g_P1[row % 864];                                 // row=(o*6+i)*144+n; %864 = i*144+n
    float pv = __fdiv_rn(p - mn, den);                         // norm01 (runtime denom: true div)
    pack_row(rm_in2 + (size_t)row * 1280, thr_of(pv), g_X2 + row*40, lane);
}

// ---------------- kernel 4: fused tail (conv2+pool2 -> packX3 -> fc3 -> packX4 -> fc4 -> packX5 -> fc5) ----------------
#define TAIL_BLOCKS 128
__global__ void k_tail(const float* __restrict__ b2,
                       const float* __restrict__ rm_x3, const float* __restrict__ rm_x4,
                       const float* __restrict__ rm_x5, float* __restrict__ out) {
    __shared__ int shi[256];
    __shared__ float shf[8];
    int t = threadIdx.x;
    int lane = t & 31;
    int wid = t >> 5;
    int gw = blockIdx.x * 8 + wid;    // global warp 0..1023

    // ---- Phase A: conv2 + pool2 (+ min/max). 256 pool cells; block handles 2; warp = 1 window.
    {
        int cellIdx = blockIdx.x * 2 + (wid >> 2);     // 0..255
        int o = cellIdx >> 4, rem = cellIdx & 15, pr = rem >> 2, pc = rem & 3;
        int win = wid & 3;
        int r = 2*pr + (win >> 1), c = 2*pc + (win & 1);
        const uint4* xb = reinterpret_cast<const uint4*>(g_X2 + o*6*144*40);
        const uint4* wb = reinterpret_cast<const uint4*>(g_W2 + o*6*25*40);
        int ham = 0;
#pragma unroll
        for (int i = 0; i < 6; ++i) {
            const uint4* xi = xb + i*144*10;
            const uint4* wi = wb + i*25*10;
            for (int q = lane; q < 250; q += 32) {     // (tap k, quad) flattened
                int k = q / 10, quad = q - 10*k;
                int n = (r + k/5)*12 + (c + k%5);
                ham += popc4(xi[n*10 + quad], wi[k*10 + quad]);
            }
        }
        ham = __reduce_add_sync(FULLMASK, ham);
        if (lane == 0) {
            float cnt = (float)(192000 - ham);
            float q = __fmul_rn(cnt, (1.0f/192000.0f));
            float y = __fsub_rn(__fmul_rn(2.0f, q), 1.0f);
            float v = __fadd_rn(__fmul_rn(y, 150.0f), b2[o]);
            shf[wid] = fmaxf(v, 0.0f);
        }
        __syncthreads();
        if (t < 2) {
            int ci = blockIdx.x * 2 + t;
            float m = fmaxf(fmaxf(shf[t*4+0], shf[t*4+1]), fmaxf(shf[t*4+2], shf[t*4+3]));
            g_P2[ci] = m;
            atomicMin(&g_mm[2], __float_as_uint(m));
            atomicMax(&g_mm[3], __float_as_uint(m));
        }
    }
    grid_bar(TAIL_BLOCKS);

    // ---- Phase B: pack X3 (256 rows from rm_x3)
    {
        float mn = __uint_as_float(g_mm[2]);
        float mx = __uint_as_float(g_mm[3]);
        float den = mx - mn;
        if (gw < 256) {
            float pv = __fdiv_rn(g_P2[gw] - mn, den);
            pack_row(rm_x3 + (size_t)gw * 1280, thr_of(pv), g_X3 + gw*40, lane);
        }
    }
    grid_bar(TAIL_BLOCKS);

    // ---- Phase C: fc3 (120 outputs; block m, thread t = input n)
    {
        int h = 0;
        if (blockIdx.x < 120) {
            const uint4* xr = reinterpret_cast<const uint4*>(g_X3 + t*40);
            const uint4* sr = reinterpret_cast<const uint4*>(g_SW3 + (blockIdx.x*256 + t)*40);
#pragma unroll
            for (int q = 0; q < 10; ++q) h += popc4(xr[q], sr[q]);
        }
        shi[t] = h; __syncthreads();
        for (int s = 128; s; s >>= 1) { if (t < s) shi[t] += shi[t + s]; __syncthreads(); }
        if (t == 0 && blockIdx.x < 120) {
            float cnt = (float)(327680 - shi[0] + g_pos3[blockIdx.x]);   // 256*1280 - H + pos
            float q = __fmul_rn(cnt, (1.0f/328960.0f));                  // 257*1280
            float o3 = __fmul_rn(__fsub_rn(__fmul_rn(2.0f, q), 1.0f), 257.0f);
            float rv = fmaxf(o3, 0.0f);
            g_f1[blockIdx.x] = rv;
            atomicMin(&g_mm[4], __float_as_uint(rv));
            atomicMax(&g_mm[5], __float_as_uint(rv));
        }
    }
    grid_bar(TAIL_BLOCKS);

    // ---- Phase D: pack X4 (120 rows from rm_x4)
    {
        float mn = __uint_as_float(g_mm[4]);
        float mx = __uint_as_float(g_mm[5]);
        float den = mx - mn;
        if (gw < 120) {
            float pv = __fdiv_rn(g_f1[gw] - mn, den);
            pack_row(rm_x4 + (size_t)gw * 1280, thr_of(pv), g_X4 + gw*40, lane);
        }
    }
    grid_bar(TAIL_BLOCKS);

    // ---- Phase E: fc4 (84 outputs; block m, thread t<120 = input n)
    {
        int h = 0;
        if (blockIdx.x < 84 && t < 120) {
            const uint4* xr = reinterpret_cast<const uint4*>(g_X4 + t*40);
            const uint4* sr = reinterpret_cast<const uint4*>(g_SW4 + (blockIdx.x*120 + t)*40);
#pragma unroll
            for (int q = 0; q < 10; ++q) h += popc4(xr[q], sr[q]);
        }
        shi[t] = h; __syncthreads();
        for (int s = 128; s; s >>= 1) { if (t < s) shi[t] += shi[t + s]; __syncthreads(); }
        if (t == 0 && blockIdx.x < 84) {
            float cnt = (float)(153600 - shi[0] + g_pos4[blockIdx.x]);   // 120*1280 - H + pos
            float q = __fmul_rn(cnt, (1.0f/154880.0f));                  // 121*1280
            float o4 = __fmul_rn(__fsub_rn(__fmul_rn(2.0f, q), 1.0f), 121.0f);
            float rv = fmaxf(o4, 0.0f);
            g_f2[blockIdx.x] = rv;
            atomicMin(&g_mm[6], __float_as_uint(rv));
            atomicMax(&g_mm[7], __float_as_uint(rv));
        }
    }
    grid_bar(TAIL_BLOCKS);

    // ---- Phase F: pack X5 (84 rows from rm_x5)
    {
        float mn = __uint_as_float(g_mm[6]);
        float mx = __uint_as_float(g_mm[7]);
        float den = mx - mn;
        if (gw < 84) {
            float pv = __fdiv_rn(g_f2[gw] - mn, den);
            pack_row(rm_x5 + (size_t)gw * 1280, thr_of(pv), g_X5 + gw*40, lane);
        }
    }
    grid_bar(TAIL_BLOCKS);

    // ---- Phase G: fc5 (10 outputs; block m, thread t<84 = input n)
    {
        int h = 0;
        if (blockIdx.x < 10 && t < 84) {
            const uint4* xr = reinterpret_cast<const uint4*>(g_X5 + t*40);
            const uint4* sr = reinterpret_cast<const uint4*>(g_SW5 + (blockIdx.x*84 + t)*40);
#pragma unroll
            for (int q = 0; q < 10; ++q) h += popc4(xr[q], sr[q]);
        }
        shi[t] = h; __syncthreads();
        for (int s = 128; s; s >>= 1) { if (t < s) shi[t] += shi[t + s]; __syncthreads(); }
        if (t == 0 && blockIdx.x < 10) {
            float cnt = (float)(107520 - shi[0] + g_pos5[blockIdx.x]);   // 84*1280 - H + pos
            float q = __fmul_rn(cnt, (1.0f/108800.0f));                  // 85*1280
            out[blockIdx.x] = __fmul_rn(__fsub_rn(__fmul_rn(2.0f, q), 1.0f), 85.0f);
        }
    }
}

// ---------------- launch ----------------
extern "C" void kernel_launch(void* const* d_in, const int* in_sizes, int n_in,
                              void* d_out, int out_size) {
    const float* img    = (const float*)d_in[0];
    const float* w1     = (const float*)d_in[1];
    const float* b1     = (const float*)d_in[2];
    const float* w2     = (const float*)d_in[3];
    const float* b2     = (const float*)d_in[4];
    const float* wfc3   = (const float*)d_in[5];
    const float* bfc3   = (const float*)d_in[6];
    const float* wfc4   = (const float*)d_in[7];
    const float* bfc4   = (const float*)d_in[8];
    const float* wfc5   = (const float*)d_in[9];
    const float* bfc5   = (const float*)d_in[10];
    const float* rm_in1 = (const float*)d_in[11];
    const float* rm_k1  = (const float*)d_in[12];
    const float* rm_in2 = (const float*)d_in[13];
    const float* rm_k2  = (const float*)d_in[14];
    const float* rm_x3  = (const float*)d_in[15];
    const float* rm_w3  = (const float*)d_in[16];
    const float* rm_b3  = (const float*)d_in[17];
    const float* rm_x4  = (const float*)d_in[18];
    const float* rm_w4  = (const float*)d_in[19];
    const float* rm_b4  = (const float*)d_in[20];
    const float* rm_x5  = (const float*)d_in[21];
    const float* rm_w5  = (const float*)d_in[22];
    const float* rm_b5  = (const float*)d_in[23];
    float* out = (float*)d_out;

    k_pack_static_all<<<2048, 256>>>(img, w1, w2, wfc3, wfc4, wfc5, bfc3, bfc4, bfc5,
                                     rm_in1, rm_k1, rm_k2, rm_w3, rm_w4, rm_w5,
                                     rm_b3, rm_b4, rm_b5);
    k_conv1pool1<<<108, 256>>>(b1);
    k_pack_X2<<<1728, 256>>>(rm_in2);
    k_tail<<<TAIL_BLOCKS, 256>>>(b2, rm_x3, rm_x4, rm_x5, out);
}

// round 8
// speedup vs baseline: 1.7591x; 1.0150x over previous
#include <cuda_runtime.h>

#define FULLMASK 0xffffffffu
#define NB 148
#define NT 512
#define NWARP (NB*16)

// ---------------- scratch (__device__ globals; no allocation allowed) ----------------
__device__ __align__(16) unsigned g_X1[6*784*40];      // packed bip(image, rm_in1)
__device__ __align__(16) unsigned g_W1[6*25*40];       // packed bip(w1, rm_k1)
__device__ __align__(16) unsigned g_W2[16*6*25*40];    // packed bip(w2, rm_k2)
__device__ __align__(16) unsigned g_X2[16*6*144*40];   // packed bip(p1norm, rm_in2)
__device__ __align__(16) unsigned g_SW3[120*256*40];   // [m][n][40]
__device__ __align__(16) unsigned g_SW4[84*120*40];    // [m][n][40]
__device__ __align__(16) unsigned g_SW5[10*84*40];     // [m][n][40]
__device__ __align__(16) unsigned g_X3[256*40];
__device__ __align__(16) unsigned g_X4[120*40];
__device__ __align__(16) unsigned g_X5[84*40];
__device__ int g_pos3[120];
__device__ int g_pos4[84];
__device__ int g_pos5[10];
__device__ float g_P1[864];       // pool1 (6,12,12) un-normalized
__device__ float g_P2[256];       // pool2 (16,4,4) un-normalized
__device__ float g_f1[120];       // relu(fc3) un-normalized
__device__ float g_f2[84];        // relu(fc4) un-normalized
__device__ unsigned g_mm[8];      // bit-punned nonneg float min/max pairs
__device__ unsigned g_flag[NB];   // per-block arrival flags (monotonic seq)
__device__ unsigned g_gen;        // release word

// ---------------- helpers ----------------

__device__ __forceinline__ int popc4(uint4 a, uint4 b) {
    return __popc(a.x ^ b.x) + __popc(a.y ^ b.y) + __popc(a.z ^ b.z) + __popc(a.w ^ b.w);
}

// Pack one bitstream row: 1280 floats -> 40 uint32 words. All loads hoisted for MLP.
__device__ __forceinline__ void pack_row(const float* __restrict__ src, float thr,
                                         unsigned* __restrict__ dst, int lane) {
    float v[40];
#pragma unroll
    for (int wd = 0; wd < 40; ++wd) v[wd] = src[wd*32 + lane];
#pragma unroll
    for (int wd = 0; wd < 40; wd += 4) {
        unsigned b0 = __ballot_sync(FULLMASK, thr > v[wd+0]);
        unsigned b1 = __ballot_sync(FULLMASK, thr > v[wd+1]);
        unsigned b2 = __ballot_sync(FULLMASK, thr > v[wd+2]);
        unsigned b3 = __ballot_sync(FULLMASK, thr > v[wd+3]);
        if (lane == 0) *reinterpret_cast<uint4*>(dst + wd) = make_uint4(b0, b1, b2, b3);
    }
}

__device__ __forceinline__ int pack_row_popc(const float* __restrict__ src, float thr, int lane) {
    float v[40];
#pragma unroll
    for (int wd = 0; wd < 40; ++wd) v[wd] = src[wd*32 + lane];
    int s = 0;
#pragma unroll
    for (int wd = 0; wd < 40; ++wd) s += __popc(__ballot_sync(FULLMASK, thr > v[wd]));
    return s;
}

__device__ __forceinline__ float thr_of(float v) {
    return __fmul_rn(__fadd_rn(v, 1.0f), 0.5f);
}

// Grid barrier via per-block flags (no RMW serialization). seq is monotonically
// increasing per call site (1,2,3,...): replay-safe because barrier N can only
// start after flag==N-1 was globally observed, so stale values can't alias.
__device__ __forceinline__ void gbar(unsigned seq) {
    __syncthreads();
    if (threadIdx.x == 0) {
        __threadfence();
        *(volatile unsigned*)&g_flag[blockIdx.x] = seq;
    }
    if (blockIdx.x == 0) {
        if (threadIdx.x < NB) {
            while (*(volatile unsigned*)&g_flag[threadIdx.x] != seq) {}
        }
        __syncthreads();
        if (threadIdx.x == 0) {
            __threadfence();
            *(volatile unsigned*)&g_gen = seq;
        }
    }
    if (threadIdx.x == 0) {
        while (*(volatile unsigned*)&g_gen != seq) {}
        __threadfence();
    }
    __syncthreads();
}

// ---------------- the one kernel ----------------
__global__ void __launch_bounds__(NT, 1) k_mega(
    const float* __restrict__ img, const float* __restrict__ w1, const float* __restrict__ b1,
    const float* __restrict__ w2, const float* __restrict__ b2,
    const float* __restrict__ wfc3, const float* __restrict__ bfc3,
    const float* __restrict__ wfc4, const float* __restrict__ bfc4,
    const float* __restrict__ wfc5, const float* __restrict__ bfc5,
    const float* __restrict__ rm_in1, const float* __restrict__ rm_k1,
    const float* __restrict__ rm_in2, const float* __restrict__ rm_k2,
    const float* __restrict__ rm_x3, const float* __restrict__ rm_w3, const float* __restrict__ rm_b3,
    const float* __restrict__ rm_x4, const float* __restrict__ rm_w4, const float* __restrict__ rm_b4,
    const float* __restrict__ rm_x5, const float* __restrict__ rm_w5, const float* __restrict__ rm_b5,
    float* __restrict__ out)
{
    __shared__ int shi[NT];
    __shared__ float shf[16];
    const int t = threadIdx.x;
    const int lane = t & 31;
    const int wid = t >> 5;
    const int gw = blockIdx.x * 16 + wid;       // global warp 0..2367

    // ======== Phase 0: init + pack X1/W1/W2 (26MB) ========
    if (blockIdx.x == 0 && t < 8)
        g_mm[t] = (t & 1) ? 0u : 0x7f800000u;   // min=+inf, max=0
    {
        const int RX1 = 6*784, RW1 = RX1 + 6*25, RW2 = RW1 + 16*6*25;  // 4704,4854,7254
        for (int row = gw; row < RW2; row += NWARP) {
            if (row < RX1) {
                pack_row(rm_in1 + (size_t)row * 1280, thr_of(img[row % 784]), g_X1 + row*40, lane);
            } else if (row < RW1) {
                int r = row - RX1;
                pack_row(rm_k1 + (size_t)r * 1280, thr_of(w1[r]), g_W1 + r*40, lane);
            } else {
                int r = row - RW1;
                pack_row(rm_k2 + (size_t)r * 1280, thr_of(w2[r]), g_W2 + r*40, lane);
            }
        }
    }
    gbar(1);

    // ======== Phase 1: conv1 + pool1 (864 warp-cells) ========
    if (gw < 864) {
        int o = gw / 144, rem = gw % 144, pr = rem / 12, pc = rem % 12;
        const uint4* xb = reinterpret_cast<const uint4*>(g_X1 + o*784*40);
        const uint4* wb = reinterpret_cast<const uint4*>(g_W1 + o*25*40);
        float bo = b1[o];
        float m = 0.0f;
#pragma unroll
        for (int win = 0; win < 4; ++win) {
            int r = 2*pr + (win >> 1), c = 2*pc + (win & 1);
            int ham = 0;
            for (int q = lane; q < 250; q += 32) {       // (tap k, quad): 25*10
                int k = q / 10, quad = q - 10*k;
                int n = (r + k/5)*28 + (c + k%5);
                ham += popc4(xb[n*10 + quad], wb[k*10 + quad]);
            }
            ham = __reduce_add_sync(FULLMASK, ham);
            float cnt = (float)(32000 - ham);
            float q2 = __fmul_rn(cnt, (1.0f/32000.0f));
            float y = __fsub_rn(__fmul_rn(2.0f, q2), 1.0f);
            float v = fmaxf(__fadd_rn(__fmul_rn(y, 25.0f), bo), 0.0f);
            m = fmaxf(m, v);
        }
        if (lane == 0) {
            g_P1[gw] = m;
            atomicMin(&g_mm[0], __float_as_uint(m));
            atomicMax(&g_mm[1], __float_as_uint(m));
        }
    }
    gbar(2);

    // ======== Phase 2: big pack — X2 (71MB) + SW3/4/5 (213MB) + bias popcounts ========
    {
        const int RX2 = 16*6*144;            // 13824
        const int RS3 = RX2 + 256*120;       // 44544
        const int RS4 = RS3 + 120*84;        // 54624
        const int RS5 = RS4 + 84*10;         // 55464
        const int RB3 = RS5 + 120;
        const int RB4 = RB3 + 84;
        const int RB5 = RB4 + 10;            // 55678
        float mn = __uint_as_float(g_mm[0]);
        float mx = __uint_as_float(g_mm[1]);
        float den = mx - mn;
        for (int row = gw; row < RB5; row += NWARP) {
            if (row < RX2) {
                float p = g_P1[row % 864];                    // row=(o*6+i)*144+n; %864 = i*144+n
                float pv = __fdiv_rn(p - mn, den);            // norm01 (runtime denom: true div)
                pack_row(rm_in2 + (size_t)row * 1280, thr_of(pv), g_X2 + row*40, lane);
            } else if (row < RS3) {
                int r = row - RX2; int n = r / 120, m = r % 120;  // rm_w3 is [n][m][l]
                pack_row(rm_w3 + (size_t)r * 1280, thr_of(wfc3[r]), g_SW3 + (m*256 + n)*40, lane);
            } else if (row < RS4) {
                int r = row - RS3; int n = r / 84, m = r % 84;
                pack_row(rm_w4 + (size_t)r * 1280, thr_of(wfc4[r]), g_SW4 + (m*120 + n)*40, lane);
            } else if (row < RS5) {
                int r = row - RS4; int n = r / 10, m = r % 10;
                pack_row(rm_w5 + (size_t)r * 1280, thr_of(wfc5[r]), g_SW5 + (m*84 + n)*40, lane);
            } else if (row < RB3) {
                int r = row - RS5;
                int s = pack_row_popc(rm_b3 + (size_t)r * 1280, thr_of(bfc3[r]), lane);
                if (lane == 0) g_pos3[r] = s;
            } else if (row < RB4) {
                int r = row - RB3;
                int s = pack_row_popc(rm_b4 + (size_t)r * 1280, thr_of(bfc4[r]), lane);
                if (lane == 0) g_pos4[r] = s;
            } else {
                int r = row - RB4;
                int s = pack_row_popc(rm_b5 + (size_t)r * 1280, thr_of(bfc5[r]), lane);
                if (lane == 0) g_pos5[r] = s;
            }
        }
    }
    gbar(3);

    // ======== Phase 3: conv2 + pool2 (256 cells x 4 windows = 1024 warp-tasks; blocks 0..63) ========
    {
        int cellIdx = blockIdx.x * 4 + (wid >> 2);     // 0..255 for blockIdx<64
        bool active = (cellIdx < 256);
        if (active) {
            int o = cellIdx >> 4, rem = cellIdx & 15, pr = rem >> 2, pc = rem & 3;
            int win = wid & 3;
            int r = 2*pr + (win >> 1), c = 2*pc + (win & 1);
            const uint4* xb = reinterpret_cast<const uint4*>(g_X2 + o*6*144*40);
            const uint4* wb = reinterpret_cast<const uint4*>(g_W2 + o*6*25*40);
            int ham = 0;
#pragma unroll
            for (int i = 0; i < 6; ++i) {
                const uint4* xi = xb + i*144*10;
                const uint4* wi = wb + i*25*10;
                for (int q = lane; q < 250; q += 32) {
                    int k = q / 10, quad = q - 10*k;
                    int n = (r + k/5)*12 + (c + k%5);
                    ham += popc4(xi[n*10 + quad], wi[k*10 + quad]);
                }
            }
            ham = __reduce_add_sync(FULLMASK, ham);
            if (lane == 0) {
                float cnt = (float)(192000 - ham);
                float q = __fmul_rn(cnt, (1.0f/192000.0f));
                float y = __fsub_rn(__fmul_rn(2.0f, q), 1.0f);
                float v = __fadd_rn(__fmul_rn(y, 150.0f), b2[o]);
                shf[wid] = fmaxf(v, 0.0f);
            }
        }
        __syncthreads();
        if (t < 4 && blockIdx.x < 64) {
            int ci = blockIdx.x * 4 + t;
            float m = fmaxf(fmaxf(shf[t*4+0], shf[t*4+1]), fmaxf(shf[t*4+2], shf[t*4+3]));
            g_P2[ci] = m;
            atomicMin(&g_mm[2], __float_as_uint(m));
            atomicMax(&g_mm[3], __float_as_uint(m));
        }
    }
    gbar(4);

    // ======== Phase 4: pack X3 (256 rows) ========
    if (gw < 256) {
        float mn = __uint_as_float(g_mm[2]);
        float mx = __uint_as_float(g_mm[3]);
        float den = mx - mn;
        float pv = __fdiv_rn(g_P2[gw] - mn, den);
        pack_row(rm_x3 + (size_t)gw * 1280, thr_of(pv), g_X3 + gw*40, lane);
    }
    gbar(5);

    // ======== Phase 5: fc3 (blocks 0..119; threads t<256 = input n) ========
    {
        int h = 0;
        if (blockIdx.x < 120 && t < 256) {
            const uint4* xr = reinterpret_cast<const uint4*>(g_X3 + t*40);
            const uint4* sr = reinterpret_cast<const uint4*>(g_SW3 + (blockIdx.x*256 + t)*40);
#pragma unroll
            for (int q = 0; q < 10; ++q) h += popc4(xr[q], sr[q]);
        }
        shi[t] = h; __syncthreads();
        for (int s = NT/2; s; s >>= 1) { if (t < s) shi[t] += shi[t + s]; __syncthreads(); }
        if (t == 0 && blockIdx.x < 120) {
            float cnt = (float)(327680 - shi[0] + g_pos3[blockIdx.x]);   // 256*1280 - H + pos
            float q = __fmul_rn(cnt, (1.0f/328960.0f));                  // 257*1280
            float o3 = __fmul_rn(__fsub_rn(__fmul_rn(2.0f, q), 1.0f), 257.0f);
            float rv = fmaxf(o3, 0.0f);
            g_f1[blockIdx.x] = rv;
            atomicMin(&g_mm[4], __float_as_uint(rv));
            atomicMax(&g_mm[5], __float_as_uint(rv));
        }
    }
    gbar(6);

    // ======== Phase 6: pack X4 (120 rows) ========
    if (gw < 120) {
        float mn = __uint_as_float(g_mm[4]);
        float mx = __uint_as_float(g_mm[5]);
        float den = mx - mn;
        float pv = __fdiv_rn(g_f1[gw] - mn, den);
        pack_row(rm_x4 + (size_t)gw * 1280, thr_of(pv), g_X4 + gw*40, lane);
    }
    gbar(7);

    // ======== Phase 7: fc4 (blocks 0..83; t<120 = input n) ========
    {
        int h = 0;
        if (blockIdx.x < 84 && t < 120) {
            const uint4* xr = reinterpret_cast<const uint4*>(g_X4 + t*40);
            const uint4* sr = reinterpret_cast<const uint4*>(g_SW4 + (blockIdx.x*120 + t)*40);
#pragma unroll
            for (int q = 0; q < 10; ++q) h += popc4(xr[q], sr[q]);
        }
        shi[t] = h; __syncthreads();
        for (int s = NT/2; s; s >>= 1) { if (t < s) shi[t] += shi[t + s]; __syncthreads(); }
        if (t == 0 && blockIdx.x < 84) {
            float cnt = (float)(153600 - shi[0] + g_pos4[blockIdx.x]);   // 120*1280 - H + pos
            float q = __fmul_rn(cnt, (1.0f/154880.0f));                  // 121*1280
            float o4 = __fmul_rn(__fsub_rn(__fmul_rn(2.0f, q), 1.0f), 121.0f);
            float rv = fmaxf(o4, 0.0f);
            g_f2[blockIdx.x] = rv;
            atomicMin(&g_mm[6], __float_as_uint(rv));
            atomicMax(&g_mm[7], __float_as_uint(rv));
        }
    }
    gbar(8);

    // ======== Phase 8: pack X5 (84 rows) ========
    if (gw < 84) {
        float mn = __uint_as_float(g_mm[6]);
        float mx = __uint_as_float(g_mm[7]);
        float den = mx - mn;
        float pv = __fdiv_rn(g_f2[gw] - mn, den);
        pack_row(rm_x5 + (size_t)gw * 1280, thr_of(pv), g_X5 + gw*40, lane);
    }
    gbar(9);

    // ======== Phase 9: fc5 (blocks 0..9; t<84 = input n) ========
    {
        int h = 0;
        if (blockIdx.x < 10 && t < 84) {
            const uint4* xr = reinterpret_cast<const uint4*>(g_X5 + t*40);
            const uint4* sr = reinterpret_cast<const uint4*>(g_SW5 + (blockIdx.x*84 + t)*40);
#pragma unroll
            for (int q = 0; q < 10; ++q) h += popc4(xr[q], sr[q]);
        }
        shi[t] = h; __syncthreads();
        for (int s = NT/2; s; s >>= 1) { if (t < s) shi[t] += shi[t + s]; __syncthreads(); }
        if (t == 0 && blockIdx.x < 10) {
            float cnt = (float)(107520 - shi[0] + g_pos5[blockIdx.x]);   // 84*1280 - H + pos
            float q = __fmul_rn(cnt, (1.0f/108800.0f));                  // 85*1280
            out[blockIdx.x] = __fmul_rn(__fsub_rn(__fmul_rn(2.0f, q), 1.0f), 85.0f);
        }
    }
}

// ---------------- launch ----------------
extern "C" void kernel_launch(void* const* d_in, const int* in_sizes, int n_in,
                              void* d_out, int out_size) {
    const float* img    = (const float*)d_in[0];
    const float* w1     = (const float*)d_in[1];
    const float* b1     = (const float*)d_in[2];
    const float* w2     = (const float*)d_in[3];
    const float* b2     = (const float*)d_in[4];
    const float* wfc3   = (const float*)d_in[5];
    const float* bfc3   = (const float*)d_in[6];
    const float* wfc4   = (const float*)d_in[7];
    const float* bfc4   = (const float*)d_in[8];
    const float* wfc5   = (const float*)d_in[9];
    const float* bfc5   = (const float*)d_in[10];
    const float* rm_in1 = (const float*)d_in[11];
    const float* rm_k1  = (const float*)d_in[12];
    const float* rm_in2 = (const float*)d_in[13];
    const float* rm_k2  = (const float*)d_in[14];
    const float* rm_x3  = (const float*)d_in[15];
    const float* rm_w3  = (const float*)d_in[16];
    const float* rm_b3  = (const float*)d_in[17];
    const float* rm_x4  = (const float*)d_in[18];
    const float* rm_w4  = (const float*)d_in[19];
    const float* rm_b4  = (const float*)d_in[20];
    const float* rm_x5  = (const float*)d_in[21];
    const float* rm_w5  = (const float*)d_in[22];
    const float* rm_b5  = (const float*)d_in[23];
    float* out = (float*)d_out;

    k_mega<<<NB, NT>>>(img, w1, b1, w2, b2, wfc3, bfc3, wfc4, bfc4, wfc5, bfc5,
                       rm_in1, rm_k1, rm_in2, rm_k2,
                       rm_x3, rm_w3, rm_b3, rm_x4, rm_w4, rm_b4, rm_x5, rm_w5, rm_b5,
                       out);
}